// round 7
// baseline (speedup 1.0000x reference)
#include <cuda_runtime.h>

#define DIM     4096
#define HALF    2048
#define NLAYERS 12

// Per-pair rotation constants packed as float2: {tan(theta/2), -sin(theta)}.
// Rotation [[c,s],[-s,c]] applied as 3 shears (3 FMAs):
//   a += th*b;  b += ns*a;  a += th*b;
__device__ float2 g_tn[NLAYERS * HALF];

__global__ void prep_kernel(const float* __restrict__ angles) {
    int i = blockIdx.x * blockDim.x + threadIdx.x;
    if (i < NLAYERS * HALF) {
        float s, c;
        sincosf(angles[i], &s, &c);
        g_tn[i] = make_float2(s / (1.0f + c), -s);
    }
}

// Per-exchange bank-conflict-free swizzles (verified by GF(2) rank analysis of
// each store/load pattern's varying address bits within a warp).
__device__ __forceinline__ int SW0(int e) { return e ^ ((e >> 5) & 3) ^ ((e >> 3) & 12); }
__device__ __forceinline__ int SW1(int e) { return e ^ ((e >> 2) & 28); }
__device__ __forceinline__ int SW2(int e) { return e ^ ((e >> 2) & 16); }

__device__ __forceinline__ void rot(float& a, float& b, float th, float ns) {
    a = fmaf(th, b, a);
    b = fmaf(ns, a, b);
    a = fmaf(th, b, a);
}

// One 2-layer phase on 4 register elements (local strides 1,2 in units of S):
// pairs: (x0,x1) (x2,x3) at stride S, then (x0,x2) (x1,x3) at stride 2S.
__device__ __forceinline__ void bf2(float& x0, float& x1, float& x2, float& x3,
                                    const float2 k[4]) {
    rot(x0, x1, k[0].x, k[0].y);
    rot(x2, x3, k[1].x, k[1].y);
    rot(x0, x2, k[2].x, k[2].y);
    rot(x1, x3, k[3].x, k[3].y);
}

__global__ __launch_bounds__(1024, 1)
void butterfly_kernel(const float* __restrict__ X, float* __restrict__ Y, int batch) {
    __shared__ float B0[DIM], B1[DIM], B2[DIM];   // 48 KB static
    const int t = threadIdx.x;

    // Phase element bases: phase ph (sh=2ph, S=1<<sh) -> e(j) = base + (j<<sh).
    const int base1 = ((t >> 2) << 4)  | (t & 3);
    const int base2 = ((t >> 4) << 6)  | (t & 15);
    const int base3 = ((t >> 6) << 8)  | (t & 63);
    const int base4 = ((t >> 8) << 10) | (t & 255);
    // base0 = 4t, base5 = t.

    // ---- one-time constant gather: 6 phases x 4 pairs (amortized ~54 rows) ----
    float2 K[6][4];
#pragma unroll
    for (int ph = 0; ph < 6; ph++) {
        const int sh = 2 * ph;
        const int S  = 1 << sh;
        int base;
        if      (ph == 0) base = 4 * t;
        else if (ph == 1) base = base1;
        else if (ph == 2) base = base2;
        else if (ph == 3) base = base3;
        else if (ph == 4) base = base4;
        else              base = t;
        const int l0 = 2 * ph, l1 = 2 * ph + 1;
        // left elements: layer l0 pairs start at base, base+2S; layer l1 at base, base+S
        const int e00 = base,          e01 = base + 2 * S;
        const int e10 = base,          e11 = base + S;
        const int p00 = ((e00 >> (l0 + 1)) << l0) | (e00 & (S - 1));
        const int p01 = ((e01 >> (l0 + 1)) << l0) | (e01 & (S - 1));
        const int p10 = ((e10 >> (l1 + 1)) << l1) | (e10 & (2 * S - 1));
        const int p11 = ((e11 >> (l1 + 1)) << l1) | (e11 & (2 * S - 1));
        K[ph][0] = g_tn[l0 * HALF + p00];
        K[ph][1] = g_tn[l0 * HALF + p01];
        K[ph][2] = g_tn[l1 * HALF + p10];
        K[ph][3] = g_tn[l1 * HALF + p11];
    }

    // E0 vectorized-store helpers: SW0(4t+w) = ((4t)^mask12) | (w^perm)
    const int perm   = (t >> 3) & 3;
    const int st0    = (4 * t) ^ ((t >> 1) & 12);   // 16B-aligned block base

    // ---- persistent row loop ----
    for (int row = blockIdx.x; row < batch; row += gridDim.x) {
        const float4 v = *reinterpret_cast<const float4*>(X + (size_t)row * DIM + 4 * t);
        float x0 = v.x, x1 = v.y, x2 = v.z, x3 = v.w;

        // L2 prefetch of next row (one 128B line per 8 threads)
        const int nrow = row + gridDim.x;
        if ((t & 7) == 0 && nrow < batch) {
            const char* q = (const char*)(X + (size_t)nrow * DIM + 4 * t);
            asm volatile("prefetch.global.L2 [%0];" :: "l"(q));
        }

        // phase 0: layers 0,1 (strides 1,2)
        bf2(x0, x1, x2, x3, K[0]);
        {   // permuted STS.128: component i holds x[i^perm]
            float a0 = x0, a1 = x1, a2 = x2, a3 = x3;
            if (perm & 1) { float u = a0; a0 = a1; a1 = u; u = a2; a2 = a3; a3 = u; }
            if (perm & 2) { float u = a0; a0 = a2; a2 = u; u = a1; a1 = a3; a3 = u; }
            *reinterpret_cast<float4*>(&B0[st0]) = make_float4(a0, a1, a2, a3);
        }
        __syncthreads();
        x0 = B0[SW0(base1)];
        x1 = B0[SW0(base1 + 4)];
        x2 = B0[SW0(base1 + 8)];
        x3 = B0[SW0(base1 + 12)];

        // phase 1: layers 2,3 (strides 4,8)
        bf2(x0, x1, x2, x3, K[1]);
        B1[SW1(base1)]      = x0;
        B1[SW1(base1 + 4)]  = x1;
        B1[SW1(base1 + 8)]  = x2;
        B1[SW1(base1 + 12)] = x3;
        __syncthreads();
        x0 = B1[SW1(base2)];
        x1 = B1[SW1(base2 + 16)];
        x2 = B1[SW1(base2 + 32)];
        x3 = B1[SW1(base2 + 48)];

        // phase 2: layers 4,5 (strides 16,32)
        bf2(x0, x1, x2, x3, K[2]);
        B2[SW2(base2)]      = x0;
        B2[SW2(base2 + 16)] = x1;
        B2[SW2(base2 + 32)] = x2;
        B2[SW2(base2 + 48)] = x3;
        __syncthreads();
        x0 = B2[SW2(base3)];
        x1 = B2[SW2(base3 + 64)];
        x2 = B2[SW2(base3 + 128)];
        x3 = B2[SW2(base3 + 192)];

        // phase 3: layers 6,7 (strides 64,128)
        bf2(x0, x1, x2, x3, K[3]);
        B0[base3]       = x0;
        B0[base3 + 64]  = x1;
        B0[base3 + 128] = x2;
        B0[base3 + 192] = x3;
        __syncthreads();
        x0 = B0[base4];
        x1 = B0[base4 + 256];
        x2 = B0[base4 + 512];
        x3 = B0[base4 + 768];

        // phase 4: layers 8,9 (strides 256,512)
        bf2(x0, x1, x2, x3, K[4]);
        B1[base4]       = x0;
        B1[base4 + 256] = x1;
        B1[base4 + 512] = x2;
        B1[base4 + 768] = x3;
        __syncthreads();
        x0 = B1[t];
        x1 = B1[t + 1024];
        x2 = B1[t + 2048];
        x3 = B1[t + 3072];

        // phase 5: layers 10,11 (strides 1024,2048)
        bf2(x0, x1, x2, x3, K[5]);

        float* y = Y + (size_t)row * DIM + t;
        y[0]    = x0;
        y[1024] = x1;
        y[2048] = x2;
        y[3072] = x3;
        // No trailing sync: next iteration's B0 store is ordered after this
        // iteration's sync 4/5, which dominate every thread's last B0/B1 reads.
    }
}

extern "C" void kernel_launch(void* const* d_in, const int* in_sizes, int n_in,
                              void* d_out, int out_size) {
    const float* x      = (const float*)d_in[0];
    const float* angles = (const float*)d_in[1];
    // left_idx/right_idx inputs are deterministic -> recomputed analytically.
    float* y = (float*)d_out;

    const int batch = in_sizes[0] / DIM;

    int nsm = 148;
    cudaDeviceGetAttribute(&nsm, cudaDevAttrMultiProcessorCount, 0);

    prep_kernel<<<(NLAYERS * HALF + 1023) / 1024, 1024>>>(angles);
    butterfly_kernel<<<nsm, 1024>>>(x, y, batch);
}

// round 8
// speedup vs baseline: 1.1347x; 1.1347x over previous
#include <cuda_runtime.h>

#define DIM  4096
#define HALF 2048

// Swizzle: XORs word-index bits {5,6,7,8} into bits {2,3,4}.
// b2^=b5, b3^=b6, b4^=b7^b8. Bijective; only touches bits <=4, so any aligned
// 32-float region is preserved (keeps warp-/pair-private smem regions private,
// and preserves 16B blocks for STS.128).
// Verified conflict-free (distinct banks per access phase) for all six
// store/load patterns used below.
__device__ __forceinline__ int SW(int e) {
    return e ^ ((e >> 3) & 28) ^ ((e >> 4) & 16);
}

// Givens rotation via 3 shears (3 FMAs): a+=th*b; b+=ns*a; a+=th*b;
// with th = tan(theta/2), ns = -sin(theta).
__device__ __forceinline__ void rot(float& a, float& b, float th, float ns) {
    a = fmaf(th, b, a);
    b = fmaf(ns, a, b);
    a = fmaf(th, b, a);
}

// 3 butterfly layers on 8 register elements (local strides 1,2,4).
__device__ __forceinline__ void bf3(float x[8], const float2 k[12]) {
#pragma unroll
    for (int lz = 0; lz < 3; lz++) {
        const int sig = 1 << lz;
#pragma unroll
        for (int kk = 0; kk < 4; kk++) {
            const int a = ((kk >> lz) << (lz + 1)) | (kk & (sig - 1));
            rot(x[a], x[a + sig], k[lz * 4 + kk].x, k[lz * 4 + kk].y);
        }
    }
}

extern __shared__ float smem[];   // 64 KB: A | Bq | C0 | C1 (16 KB each)

__global__ __launch_bounds__(512, 1)
void butterfly_kernel(const float* __restrict__ X, float* __restrict__ Y,
                      const float* __restrict__ ang, int batch)
{
    float* A  = smem;             // exchange 1: warp-private 256-float blocks
    float* Bq = smem + DIM;       // exchange 2: pair-private 512-float blocks
    float* C0 = smem + 2 * DIM;   // exchange 3: CTA-wide, ping
    float* C1 = smem + 3 * DIM;   // exchange 3: CTA-wide, pong
    const int t = threadIdx.x;

    // ---- one-time per-thread constants (amortized over ~54 rows) ----
    // No prep kernel: each thread computes its own 48 pair constants.
    float2 K[4][12];
#pragma unroll
    for (int ph = 0; ph < 4; ph++) {
#pragma unroll
        for (int lz = 0; lz < 3; lz++) {
#pragma unroll
            for (int kk = 0; kk < 4; kk++) {
                const int sig = 1 << lz;
                const int j = ((kk >> lz) << (lz + 1)) | (kk & (sig - 1));
                int e;                                   // global elem idx of pair-left
                if      (ph == 0) e = 8 * t + j;
                else if (ph == 1) e = 64 * (t >> 3) + 8 * j + (t & 7);
                else if (ph == 2) e = 512 * (t >> 6) + 64 * j + (t & 63);
                else              e = 512 * j + t;
                const int l = ph * 3 + lz;
                const int p = ((e >> (l + 1)) << l) | (e & ((1 << l) - 1));
                float s, c;
                sincosf(ang[l * HALF + p], &s, &c);
                K[ph][lz * 4 + kk] = make_float2(__fdividef(s, 1.0f + c), -s);
            }
        }
    }

    const int b1   = 64 * (t >> 3) + (t & 7);    // phase-1 base (stride 8)
    const int b2   = 512 * (t >> 6) + (t & 63);  // phase-2 base (stride 64)
    const int st0a = SW(8 * t);                  // phase-0 store (16B-aligned)
    const int st0b = SW(8 * t + 4);
    const int qbar = (t >> 6) + 1;               // named barrier id 1..8 per warp-pair

    int par = 0;
    for (int row = blockIdx.x; row < batch; row += gridDim.x, par ^= 1) {
        const float4* p0 = reinterpret_cast<const float4*>(X + (size_t)row * DIM + 8 * t);
        const float4 v0 = p0[0], v1 = p0[1];
        float x[8] = {v0.x, v0.y, v0.z, v0.w, v1.x, v1.y, v1.z, v1.w};

        // register-free L2 prefetch of the next row (one per 128B line)
        const int nrow = row + gridDim.x;
        if ((t & 3) == 0 && nrow < batch) {
            const char* q = (const char*)(X + (size_t)nrow * DIM + 8 * t);
            asm volatile("prefetch.global.L2 [%0];" :: "l"(q));
        }

        // ---- phase 0: layers 0..2 ----  exchange 1 is INTRA-WARP
        bf3(x, K[0]);
        *reinterpret_cast<float4*>(&A[st0a]) = make_float4(x[0], x[1], x[2], x[3]);
        *reinterpret_cast<float4*>(&A[st0b]) = make_float4(x[4], x[5], x[6], x[7]);
        __syncwarp();
#pragma unroll
        for (int j = 0; j < 8; j++) x[j] = A[SW(b1 + 8 * j)];

        // ---- phase 1: layers 3..5 ----  exchange 2 is per WARP-PAIR (named barrier)
        bf3(x, K[1]);
#pragma unroll
        for (int j = 0; j < 8; j++) Bq[SW(b1 + 8 * j)] = x[j];
        asm volatile("bar.sync %0, 64;" :: "r"(qbar) : "memory");
#pragma unroll
        for (int j = 0; j < 8; j++) x[j] = Bq[SW(b2 + 64 * j)];

        // ---- phase 2: layers 6..8 ----  exchange 3 is CTA-wide (the ONE full barrier)
        bf3(x, K[2]);
        float* C = par ? C1 : C0;
#pragma unroll
        for (int j = 0; j < 8; j++) C[SW(b2 + 64 * j)] = x[j];
        __syncthreads();
#pragma unroll
        for (int j = 0; j < 8; j++) x[j] = C[SW(512 * j + t)];

        // ---- phase 3: layers 9..11 ----
        bf3(x, K[3]);

        // coalesced output: element 512*j + t
        float* y = Y + (size_t)row * DIM + t;
#pragma unroll
        for (int j = 0; j < 8; j++) y[512 * j] = x[j];

        // Cross-row smem reuse safety:
        //  A (warp-private) and Bq (pair-private): next-row stores are ordered
        //  after this row's full __syncthreads for every thread.
        //  C: ping-pong by row parity; same buffer reused 2 rows later, with a
        //  full barrier in between -> safe. No trailing sync needed.
    }
}

extern "C" void kernel_launch(void* const* d_in, const int* in_sizes, int n_in,
                              void* d_out, int out_size) {
    const float* x      = (const float*)d_in[0];
    const float* angles = (const float*)d_in[1];
    // left_idx/right_idx inputs are deterministic -> recomputed analytically.
    float* y = (float*)d_out;

    const int batch = in_sizes[0] / DIM;

    int nsm = 148;
    cudaDeviceGetAttribute(&nsm, cudaDevAttrMultiProcessorCount, 0);

    const int smem_bytes = 4 * DIM * (int)sizeof(float);   // 64 KB
    cudaFuncSetAttribute(butterfly_kernel,
                         cudaFuncAttributeMaxDynamicSharedMemorySize, smem_bytes);

    butterfly_kernel<<<nsm, 512, smem_bytes>>>(x, y, angles, batch);
}